// round 12
// baseline (speedup 1.0000x reference)
#include <cuda_runtime.h>

#define B_   16
#define C_   256
#define S_   1024
#define NH   4
#define DK   64
#define NQKV 768
#define SCALE_ 0.125f

typedef unsigned long long ull;

// Scratch (allocation-free rule: device globals)
__device__ float g_q [B_*NH*S_*DK];   // [B,H,S,64], pre-scaled by SCALE_
__device__ float g_kt[B_*NH*DK*S_];   // [B,H,64,S]  (K transposed)
__device__ float g_v [B_*NH*S_*DK];   // [B,H,S,64]
__device__ float g_ao[B_*S_*C_];      // attention out, [B,S,256]

// ---- packed f32x2 helpers -------------------------------------------------
__device__ __forceinline__ void ffma2(ull &d, ull a, ull b) {
    asm("fma.rn.f32x2 %0, %1, %2, %0;" : "+l"(d) : "l"(a), "l"(b));
}
__device__ __forceinline__ void fmul2(ull &d, ull a, ull b) {
    asm("mul.rn.f32x2 %0, %1, %2;" : "=l"(d) : "l"(a), "l"(b));
}
__device__ __forceinline__ ull pack2(float x) {
    ull r; unsigned u = __float_as_uint(x);
    asm("mov.b64 %0, {%1, %1};" : "=l"(r) : "r"(u));
    return r;
}
__device__ __forceinline__ float lo2(ull v){ return __uint_as_float((unsigned)v); }
__device__ __forceinline__ float hi2(ull v){ return __uint_as_float((unsigned)(v>>32)); }
__device__ __forceinline__ ull d2u(double d){ return (ull)__double_as_longlong(d); }

// ---------------------------------------------------------------------------
// Kernel 1: QKV GEMM. out[b,s,n] = sum_c x[b,c,s]*w[c,n] + bias[n]
// Tile 128(s) x 128(n) x 16(k). 256 thr: tx(0..7) owns n cols tx*4+g*32 (+pair),
// ty(0..31) owns 4 s rows. f32x2 pairs along n. Reg double-buffered loads.
// grid (6, 8, 16).
// ---------------------------------------------------------------------------
__global__ __launch_bounds__(256, 2) void qkv_kernel(const float* __restrict__ x,
                                                     const float* __restrict__ w,
                                                     const float* __restrict__ bias) {
    __shared__ float As[16][128];   // [k][s]
    __shared__ float Bs[16][128];   // [k][n]
    const int b = blockIdx.z, s0 = blockIdx.y*128, n0 = blockIdx.x*128;
    const int tid = threadIdx.x;
    const int tx = tid & 7, ty = tid >> 3;
    const int lr = tid >> 5, lc = (tid & 31) * 4;
    const float* xA = x + b*C_*S_ + s0;
    const float* wB = w + n0;

    float4 pa0 = *(const float4*)(xA + lr*S_ + lc);
    float4 pa1 = *(const float4*)(xA + (lr+8)*S_ + lc);
    float4 pb0 = *(const float4*)(wB + lr*NQKV + lc);
    float4 pb1 = *(const float4*)(wB + (lr+8)*NQKV + lc);

    ull acc[4][8];
#pragma unroll
    for (int i = 0; i < 4; i++)
#pragma unroll
        for (int p = 0; p < 8; p++) acc[i][p] = 0ull;

    for (int k0 = 0; k0 < C_; k0 += 16) {
        *(float4*)&As[lr][lc]   = pa0;
        *(float4*)&As[lr+8][lc] = pa1;
        *(float4*)&Bs[lr][lc]   = pb0;
        *(float4*)&Bs[lr+8][lc] = pb1;
        __syncthreads();
        if (k0 + 16 < C_) {
            const float* xk = xA + (k0+16)*S_;
            const float* wk = wB + (k0+16)*NQKV;
            pa0 = *(const float4*)(xk + lr*S_ + lc);
            pa1 = *(const float4*)(xk + (lr+8)*S_ + lc);
            pb0 = *(const float4*)(wk + lr*NQKV + lc);
            pb1 = *(const float4*)(wk + (lr+8)*NQKV + lc);
        }
#pragma unroll
        for (int kk = 0; kk < 16; kk++) {
            float4 av = *(const float4*)&As[kk][ty*4];
            ull bp[8];
#pragma unroll
            for (int g = 0; g < 4; g++) {
                double2 t = *(const double2*)&Bs[kk][tx*4 + g*32];
                bp[g*2]   = d2u(t.x);
                bp[g*2+1] = d2u(t.y);
            }
            ull a0 = pack2(av.x), a1 = pack2(av.y), a2 = pack2(av.z), a3 = pack2(av.w);
#pragma unroll
            for (int p = 0; p < 8; p++) {
                ffma2(acc[0][p], a0, bp[p]);
                ffma2(acc[1][p], a1, bp[p]);
                ffma2(acc[2][p], a2, bp[p]);
                ffma2(acc[3][p], a3, bp[p]);
            }
        }
        __syncthreads();
    }

    // Epilogue: add bias, scatter to q (pre-scaled), kt (transposed), v.
    // Each 4-col group never straddles a 64-multiple boundary (all offsets %4==0).
#pragma unroll
    for (int g = 0; g < 4; g++) {
        const int n = n0 + tx*4 + g*32;
        const int h = n / 192;
        const int e = n - h*192;
        const float4 bb = *(const float4*)&bias[n];
#pragma unroll
        for (int i = 0; i < 4; i++) {
            const int s = s0 + ty*4 + i;
            float v0 = lo2(acc[i][2*g])   + bb.x;
            float v1 = hi2(acc[i][2*g])   + bb.y;
            float v2 = lo2(acc[i][2*g+1]) + bb.z;
            float v3 = hi2(acc[i][2*g+1]) + bb.w;
            if (e < 64) {
                *(float4*)&g_q[((b*NH+h)*S_+s)*DK + e] =
                    make_float4(v0*SCALE_, v1*SCALE_, v2*SCALE_, v3*SCALE_);
            } else if (e < 128) {
                float* kt = g_kt + ((b*NH+h)*DK + (e-64))*S_ + s;
                kt[0] = v0; kt[S_] = v1; kt[2*S_] = v2; kt[3*S_] = v3;
            } else {
                *(float4*)&g_v[((b*NH+h)*S_+s)*DK + (e-128)] =
                    make_float4(v0, v1, v2, v3);
            }
        }
    }
}

// ---------------------------------------------------------------------------
// Kernel 2: flash attention. i-tile 128, j-tile 64. 256 thr:
// tx(0..7) owns j/d cols tx*4+g*32 (g<2), ty(0..31) owns 4 i rows.
// Row softmax reduced over the 8 tx lanes (contiguous within quarter-warp).
// 96KB dynamic smem: Qs[128][64], KTs[64][64], Vs[64][64], Ps[128][64].
// grid (8, 4, 16).
// ---------------------------------------------------------------------------
__global__ __launch_bounds__(256, 2) void attn_kernel() {
    extern __shared__ float sm[];
    float (*Qs)[64]  = (float(*)[64])(sm);
    float (*KTs)[64] = (float(*)[64])(sm + 128*64);
    float (*Vs)[64]  = (float(*)[64])(sm + 128*64 + 64*64);
    float (*Ps)[64]  = (float(*)[64])(sm + 128*64 + 2*64*64);

    const int i0 = blockIdx.x * 128;
    const int h  = blockIdx.y, b = blockIdx.z;
    const int tid = threadIdx.x, tx = tid & 7, ty = tid >> 3;

    const float* qb  = g_q  + ((b*NH+h)*S_ + i0)*DK;
    const float* ktb = g_kt + (b*NH+h)*DK*S_;
    const float* vb  = g_v  + (b*NH+h)*S_*DK;

#pragma unroll
    for (int t = 0; t < 8; t++) {
        int idx = tid + t*256;
        int r = idx >> 4, c = (idx & 15)*4;
        *(float4*)&Qs[r][c] = *(const float4*)(qb + r*DK + c);
    }

    float m[4], l[4];
    ull o[4][4];
#pragma unroll
    for (int i = 0; i < 4; i++) {
        m[i] = -1e30f; l[i] = 0.f;
#pragma unroll
        for (int p = 0; p < 4; p++) o[i][p] = 0ull;
    }

    for (int j0 = 0; j0 < S_; j0 += 64) {
        __syncthreads();   // prev iter's KTs/Vs/Ps reads done (also covers Qs fill)
#pragma unroll
        for (int t = 0; t < 4; t++) {
            int idx = tid + t*256;
            int r = idx >> 4, c = (idx & 15)*4;
            *(float4*)&KTs[r][c] = *(const float4*)(ktb + r*S_ + j0 + c);
            *(float4*)&Vs[r][c]  = *(const float4*)(vb + (j0+r)*DK + c);
        }
        __syncthreads();

        // S = Q * K^T  (Q already scaled)
        ull sacc[4][4];
#pragma unroll
        for (int i = 0; i < 4; i++)
#pragma unroll
            for (int p = 0; p < 4; p++) sacc[i][p] = 0ull;

#pragma unroll 4
        for (int d4 = 0; d4 < 64; d4 += 4) {
            float q4[4][4];
#pragma unroll
            for (int i = 0; i < 4; i++)
                *(float4*)q4[i] = *(const float4*)&Qs[ty*4+i][d4];
#pragma unroll
            for (int u = 0; u < 4; u++) {
                double2 t0 = *(const double2*)&KTs[d4+u][tx*4];
                double2 t1 = *(const double2*)&KTs[d4+u][tx*4+32];
                ull b0 = d2u(t0.x), b1 = d2u(t0.y), b2 = d2u(t1.x), b3 = d2u(t1.y);
#pragma unroll
                for (int i = 0; i < 4; i++) {
                    ull a = pack2(q4[i][u]);
                    ffma2(sacc[i][0], a, b0);
                    ffma2(sacc[i][1], a, b1);
                    ffma2(sacc[i][2], a, b2);
                    ffma2(sacc[i][3], a, b3);
                }
            }
        }

        // online softmax (per row; 8 elements/thread + 8-lane shfl reduce)
#pragma unroll
        for (int i = 0; i < 4; i++) {
            float e[8];
#pragma unroll
            for (int p = 0; p < 4; p++) { e[2*p] = lo2(sacc[i][p]); e[2*p+1] = hi2(sacc[i][p]); }
            float mx = e[0];
#pragma unroll
            for (int p = 1; p < 8; p++) mx = fmaxf(mx, e[p]);
#pragma unroll
            for (int off = 1; off < 8; off <<= 1)
                mx = fmaxf(mx, __shfl_xor_sync(0xffffffffu, mx, off));
            const float mnew = fmaxf(m[i], mx);
            const float al   = __expf(m[i] - mnew);
            float rs = 0.f;
#pragma unroll
            for (int p = 0; p < 8; p++) { e[p] = __expf(e[p] - mnew); rs += e[p]; }
#pragma unroll
            for (int off = 1; off < 8; off <<= 1)
                rs += __shfl_xor_sync(0xffffffffu, rs, off);
            l[i] = l[i]*al + rs;
            m[i] = mnew;
            ull alp = pack2(al);
#pragma unroll
            for (int p = 0; p < 4; p++) fmul2(o[i][p], o[i][p], alp);
            *(float4*)&Ps[ty*4+i][tx*4]    = make_float4(e[0], e[1], e[2], e[3]);
            *(float4*)&Ps[ty*4+i][tx*4+32] = make_float4(e[4], e[5], e[6], e[7]);
        }
        __syncthreads();

        // O += P * V
#pragma unroll 4
        for (int j4 = 0; j4 < 64; j4 += 4) {
            float p4[4][4];
#pragma unroll
            for (int i = 0; i < 4; i++)
                *(float4*)p4[i] = *(const float4*)&Ps[ty*4+i][j4];
#pragma unroll
            for (int u = 0; u < 4; u++) {
                double2 t0 = *(const double2*)&Vs[j4+u][tx*4];
                double2 t1 = *(const double2*)&Vs[j4+u][tx*4+32];
                ull b0 = d2u(t0.x), b1 = d2u(t0.y), b2 = d2u(t1.x), b3 = d2u(t1.y);
#pragma unroll
                for (int i = 0; i < 4; i++) {
                    ull a = pack2(p4[i][u]);
                    ffma2(o[i][0], a, b0);
                    ffma2(o[i][1], a, b1);
                    ffma2(o[i][2], a, b2);
                    ffma2(o[i][3], a, b3);
                }
            }
        }
    }

    float* aob = g_ao + (b*S_ + i0)*C_ + h*DK;
#pragma unroll
    for (int i = 0; i < 4; i++) {
        const float inv = 1.0f / l[i];
        float* dst = aob + (ty*4+i)*C_;
        *(float4*)(dst + tx*4) = make_float4(lo2(o[i][0])*inv, hi2(o[i][0])*inv,
                                             lo2(o[i][1])*inv, hi2(o[i][1])*inv);
        *(float4*)(dst + tx*4 + 32) = make_float4(lo2(o[i][2])*inv, hi2(o[i][2])*inv,
                                                  lo2(o[i][3])*inv, hi2(o[i][3])*inv);
    }
}

// ---------------------------------------------------------------------------
// Kernel 3: out-proj + bias + residual. out[b,c,s] = ao[b,s,:] @ w_out[:,c]
// + b_out[c] + x[b,c,s]. Tile 128(c) x 128(s) x 16(n). Same micro layout.
// grid (2, 8, 16).
// ---------------------------------------------------------------------------
__global__ __launch_bounds__(256, 2) void proj_kernel(const float* __restrict__ wo,
                                                      const float* __restrict__ bo,
                                                      const float* __restrict__ x,
                                                      float* __restrict__ out) {
    __shared__ float Ws[16][128];   // [k=n][c]
    __shared__ float At[16][132];   // [k=n][s], padded (16B-aligned rows)
    const int c0 = blockIdx.x*128, s0 = blockIdx.y*128, b = blockIdx.z;
    const int tid = threadIdx.x;
    const int tx = tid & 7, ty = tid >> 3;
    const int lr = tid >> 5, lc = (tid & 31)*4;
    const int srow0 = tid >> 2, kc0 = (tid & 3)*4;   // At transpose loader
    const float* aob = g_ao + (b*S_ + s0)*C_;

    float4 pw0 = *(const float4*)(wo + lr*C_ + c0 + lc);
    float4 pw1 = *(const float4*)(wo + (lr+8)*C_ + c0 + lc);
    float4 pa0 = *(const float4*)(aob + srow0*C_ + kc0);
    float4 pa1 = *(const float4*)(aob + (srow0+64)*C_ + kc0);

    ull acc[4][8];
#pragma unroll
    for (int i = 0; i < 4; i++)
#pragma unroll
        for (int p = 0; p < 8; p++) acc[i][p] = 0ull;

    for (int k0 = 0; k0 < C_; k0 += 16) {
        *(float4*)&Ws[lr][lc]   = pw0;
        *(float4*)&Ws[lr+8][lc] = pw1;
        At[kc0+0][srow0] = pa0.x; At[kc0+1][srow0] = pa0.y;
        At[kc0+2][srow0] = pa0.z; At[kc0+3][srow0] = pa0.w;
        At[kc0+0][srow0+64] = pa1.x; At[kc0+1][srow0+64] = pa1.y;
        At[kc0+2][srow0+64] = pa1.z; At[kc0+3][srow0+64] = pa1.w;
        __syncthreads();
        if (k0 + 16 < C_) {
            pw0 = *(const float4*)(wo + (k0+16+lr)*C_ + c0 + lc);
            pw1 = *(const float4*)(wo + (k0+16+lr+8)*C_ + c0 + lc);
            pa0 = *(const float4*)(aob + srow0*C_ + k0+16 + kc0);
            pa1 = *(const float4*)(aob + (srow0+64)*C_ + k0+16 + kc0);
        }
#pragma unroll
        for (int kk = 0; kk < 16; kk++) {
            float4 av = *(const float4*)&Ws[kk][ty*4];
            ull bp[8];
#pragma unroll
            for (int g = 0; g < 4; g++) {
                double2 t = *(const double2*)&At[kk][tx*4 + g*32];
                bp[g*2]   = d2u(t.x);
                bp[g*2+1] = d2u(t.y);
            }
            ull a0 = pack2(av.x), a1 = pack2(av.y), a2 = pack2(av.z), a3 = pack2(av.w);
#pragma unroll
            for (int p = 0; p < 8; p++) {
                ffma2(acc[0][p], a0, bp[p]);
                ffma2(acc[1][p], a1, bp[p]);
                ffma2(acc[2][p], a2, bp[p]);
                ffma2(acc[3][p], a3, bp[p]);
            }
        }
        __syncthreads();
    }

#pragma unroll
    for (int i = 0; i < 4; i++) {
        const int c = c0 + ty*4 + i;
        const float bias = bo[c];
        const float* xr = x   + (b*C_ + c)*S_ + s0;
        float*       orr = out + (b*C_ + c)*S_ + s0;
#pragma unroll
        for (int g = 0; g < 4; g++) {
            const int sc = tx*4 + g*32;
            float4 xv = *(const float4*)(xr + sc);
            float4 r;
            r.x = lo2(acc[i][2*g])   + bias + xv.x;
            r.y = hi2(acc[i][2*g])   + bias + xv.y;
            r.z = lo2(acc[i][2*g+1]) + bias + xv.z;
            r.w = hi2(acc[i][2*g+1]) + bias + xv.w;
            *(float4*)(orr + sc) = r;
        }
    }
}

// ---------------------------------------------------------------------------
extern "C" void kernel_launch(void* const* d_in, const int* in_sizes, int n_in,
                              void* d_out, int out_size) {
    const float* x     = (const float*)d_in[0];
    const float* w_qkv = (const float*)d_in[1];
    const float* b_qkv = (const float*)d_in[2];
    const float* w_out = (const float*)d_in[3];
    const float* b_out = (const float*)d_in[4];
    float* out = (float*)d_out;

    cudaFuncSetAttribute(attn_kernel, cudaFuncAttributeMaxDynamicSharedMemorySize, 98304);

    qkv_kernel <<<dim3(NQKV/128, S_/128, B_), 256>>>(x, w_qkv, b_qkv);
    attn_kernel<<<dim3(S_/128, NH, B_), 256, 98304>>>();
    proj_kernel<<<dim3(C_/128, S_/128, B_), 256>>>(w_out, b_out, x, out);
}

// round 13
// speedup vs baseline: 1.0017x; 1.0017x over previous
#include <cuda_runtime.h>

#define B_   16
#define C_   256
#define S_   1024
#define NH   4
#define DK   64
#define NQKV 768
#define SCALE_ 0.125f

typedef unsigned long long ull;

// Scratch (allocation-free rule: device globals)
__device__ float g_q [B_*NH*S_*DK];   // [B,H,S,64], pre-scaled by SCALE_
__device__ float g_kt[B_*NH*DK*S_];   // [B,H,64,S]  (K transposed)
__device__ float g_v [B_*NH*S_*DK];   // [B,H,S,64]
__device__ float g_ao[B_*S_*C_];      // attention out, [B,S,256]

// ---- packed f32x2 helpers -------------------------------------------------
__device__ __forceinline__ void ffma2(ull &d, ull a, ull b) {
    asm("fma.rn.f32x2 %0, %1, %2, %0;" : "+l"(d) : "l"(a), "l"(b));
}
__device__ __forceinline__ void fmul2(ull &d, ull a, ull b) {
    asm("mul.rn.f32x2 %0, %1, %2;" : "=l"(d) : "l"(a), "l"(b));
}
__device__ __forceinline__ ull pack2(float x) {
    ull r; unsigned u = __float_as_uint(x);
    asm("mov.b64 %0, {%1, %1};" : "=l"(r) : "r"(u));
    return r;
}
__device__ __forceinline__ float lo2(ull v){ return __uint_as_float((unsigned)v); }
__device__ __forceinline__ float hi2(ull v){ return __uint_as_float((unsigned)(v>>32)); }
__device__ __forceinline__ ull d2u(double d){ return (ull)__double_as_longlong(d); }

// ---------------------------------------------------------------------------
// Kernel 1: QKV GEMM. out[b,s,n] = sum_c x[b,c,s]*w[c,n] + bias[n]
// Tile 128(s) x 128(n) x 16(k). 256 thr: tx(0..7) owns n cols tx*4+g*32 (+pair),
// ty(0..31) owns 4 s rows. f32x2 pairs along n. Reg double-buffered loads.
// grid (6, 8, 16).
// ---------------------------------------------------------------------------
__global__ __launch_bounds__(256, 2) void qkv_kernel(const float* __restrict__ x,
                                                     const float* __restrict__ w,
                                                     const float* __restrict__ bias) {
    __shared__ float As[16][128];   // [k][s]
    __shared__ float Bs[16][128];   // [k][n]
    const int b = blockIdx.z, s0 = blockIdx.y*128, n0 = blockIdx.x*128;
    const int tid = threadIdx.x;
    const int tx = tid & 7, ty = tid >> 3;
    const int lr = tid >> 5, lc = (tid & 31) * 4;
    const float* xA = x + b*C_*S_ + s0;
    const float* wB = w + n0;

    float4 pa0 = *(const float4*)(xA + lr*S_ + lc);
    float4 pa1 = *(const float4*)(xA + (lr+8)*S_ + lc);
    float4 pb0 = *(const float4*)(wB + lr*NQKV + lc);
    float4 pb1 = *(const float4*)(wB + (lr+8)*NQKV + lc);

    ull acc[4][8];
#pragma unroll
    for (int i = 0; i < 4; i++)
#pragma unroll
        for (int p = 0; p < 8; p++) acc[i][p] = 0ull;

    for (int k0 = 0; k0 < C_; k0 += 16) {
        *(float4*)&As[lr][lc]   = pa0;
        *(float4*)&As[lr+8][lc] = pa1;
        *(float4*)&Bs[lr][lc]   = pb0;
        *(float4*)&Bs[lr+8][lc] = pb1;
        __syncthreads();
        if (k0 + 16 < C_) {
            const float* xk = xA + (k0+16)*S_;
            const float* wk = wB + (k0+16)*NQKV;
            pa0 = *(const float4*)(xk + lr*S_ + lc);
            pa1 = *(const float4*)(xk + (lr+8)*S_ + lc);
            pb0 = *(const float4*)(wk + lr*NQKV + lc);
            pb1 = *(const float4*)(wk + (lr+8)*NQKV + lc);
        }
#pragma unroll
        for (int kk = 0; kk < 16; kk++) {
            float4 av = *(const float4*)&As[kk][ty*4];
            ull bp[8];
#pragma unroll
            for (int g = 0; g < 4; g++) {
                double2 t = *(const double2*)&Bs[kk][tx*4 + g*32];
                bp[g*2]   = d2u(t.x);
                bp[g*2+1] = d2u(t.y);
            }
            ull a0 = pack2(av.x), a1 = pack2(av.y), a2 = pack2(av.z), a3 = pack2(av.w);
#pragma unroll
            for (int p = 0; p < 8; p++) {
                ffma2(acc[0][p], a0, bp[p]);
                ffma2(acc[1][p], a1, bp[p]);
                ffma2(acc[2][p], a2, bp[p]);
                ffma2(acc[3][p], a3, bp[p]);
            }
        }
        __syncthreads();
    }

    // Epilogue: add bias, scatter to q (pre-scaled), kt (transposed), v.
    // Each 4-col group never straddles a 64-multiple boundary (all offsets %4==0).
#pragma unroll
    for (int g = 0; g < 4; g++) {
        const int n = n0 + tx*4 + g*32;
        const int h = n / 192;
        const int e = n - h*192;
        const float4 bb = *(const float4*)&bias[n];
#pragma unroll
        for (int i = 0; i < 4; i++) {
            const int s = s0 + ty*4 + i;
            float v0 = lo2(acc[i][2*g])   + bb.x;
            float v1 = hi2(acc[i][2*g])   + bb.y;
            float v2 = lo2(acc[i][2*g+1]) + bb.z;
            float v3 = hi2(acc[i][2*g+1]) + bb.w;
            if (e < 64) {
                *(float4*)&g_q[((b*NH+h)*S_+s)*DK + e] =
                    make_float4(v0*SCALE_, v1*SCALE_, v2*SCALE_, v3*SCALE_);
            } else if (e < 128) {
                float* kt = g_kt + ((b*NH+h)*DK + (e-64))*S_ + s;
                kt[0] = v0; kt[S_] = v1; kt[2*S_] = v2; kt[3*S_] = v3;
            } else {
                *(float4*)&g_v[((b*NH+h)*S_+s)*DK + (e-128)] =
                    make_float4(v0, v1, v2, v3);
            }
        }
    }
}

// ---------------------------------------------------------------------------
// Kernel 2: flash attention. i-tile 128, j-tile 64. 256 thr:
// tx(0..7) owns j/d cols tx*4+g*32 (g<2), ty(0..31) owns 4 i rows.
// Row softmax reduced over the 8 tx lanes (contiguous within quarter-warp).
// 96KB dynamic smem: Qs[128][64], KTs[64][64], Vs[64][64], Ps[128][64].
// grid (8, 4, 16).
// ---------------------------------------------------------------------------
__global__ __launch_bounds__(256, 2) void attn_kernel() {
    extern __shared__ float sm[];
    float (*Qs)[64]  = (float(*)[64])(sm);
    float (*KTs)[64] = (float(*)[64])(sm + 128*64);
    float (*Vs)[64]  = (float(*)[64])(sm + 128*64 + 64*64);
    float (*Ps)[64]  = (float(*)[64])(sm + 128*64 + 2*64*64);

    const int i0 = blockIdx.x * 128;
    const int h  = blockIdx.y, b = blockIdx.z;
    const int tid = threadIdx.x, tx = tid & 7, ty = tid >> 3;

    const float* qb  = g_q  + ((b*NH+h)*S_ + i0)*DK;
    const float* ktb = g_kt + (b*NH+h)*DK*S_;
    const float* vb  = g_v  + (b*NH+h)*S_*DK;

#pragma unroll
    for (int t = 0; t < 8; t++) {
        int idx = tid + t*256;
        int r = idx >> 4, c = (idx & 15)*4;
        *(float4*)&Qs[r][c] = *(const float4*)(qb + r*DK + c);
    }

    float m[4], l[4];
    ull o[4][4];
#pragma unroll
    for (int i = 0; i < 4; i++) {
        m[i] = -1e30f; l[i] = 0.f;
#pragma unroll
        for (int p = 0; p < 4; p++) o[i][p] = 0ull;
    }

    for (int j0 = 0; j0 < S_; j0 += 64) {
        __syncthreads();   // prev iter's KTs/Vs/Ps reads done (also covers Qs fill)
#pragma unroll
        for (int t = 0; t < 4; t++) {
            int idx = tid + t*256;
            int r = idx >> 4, c = (idx & 15)*4;
            *(float4*)&KTs[r][c] = *(const float4*)(ktb + r*S_ + j0 + c);
            *(float4*)&Vs[r][c]  = *(const float4*)(vb + (j0+r)*DK + c);
        }
        __syncthreads();

        // S = Q * K^T  (Q already scaled)
        ull sacc[4][4];
#pragma unroll
        for (int i = 0; i < 4; i++)
#pragma unroll
            for (int p = 0; p < 4; p++) sacc[i][p] = 0ull;

#pragma unroll 4
        for (int d4 = 0; d4 < 64; d4 += 4) {
            float q4[4][4];
#pragma unroll
            for (int i = 0; i < 4; i++)
                *(float4*)q4[i] = *(const float4*)&Qs[ty*4+i][d4];
#pragma unroll
            for (int u = 0; u < 4; u++) {
                double2 t0 = *(const double2*)&KTs[d4+u][tx*4];
                double2 t1 = *(const double2*)&KTs[d4+u][tx*4+32];
                ull b0 = d2u(t0.x), b1 = d2u(t0.y), b2 = d2u(t1.x), b3 = d2u(t1.y);
#pragma unroll
                for (int i = 0; i < 4; i++) {
                    ull a = pack2(q4[i][u]);
                    ffma2(sacc[i][0], a, b0);
                    ffma2(sacc[i][1], a, b1);
                    ffma2(sacc[i][2], a, b2);
                    ffma2(sacc[i][3], a, b3);
                }
            }
        }

        // online softmax (per row; 8 elements/thread + 8-lane shfl reduce)
#pragma unroll
        for (int i = 0; i < 4; i++) {
            float e[8];
#pragma unroll
            for (int p = 0; p < 4; p++) { e[2*p] = lo2(sacc[i][p]); e[2*p+1] = hi2(sacc[i][p]); }
            float mx = e[0];
#pragma unroll
            for (int p = 1; p < 8; p++) mx = fmaxf(mx, e[p]);
#pragma unroll
            for (int off = 1; off < 8; off <<= 1)
                mx = fmaxf(mx, __shfl_xor_sync(0xffffffffu, mx, off));
            const float mnew = fmaxf(m[i], mx);
            const float al   = __expf(m[i] - mnew);
            float rs = 0.f;
#pragma unroll
            for (int p = 0; p < 8; p++) { e[p] = __expf(e[p] - mnew); rs += e[p]; }
#pragma unroll
            for (int off = 1; off < 8; off <<= 1)
                rs += __shfl_xor_sync(0xffffffffu, rs, off);
            l[i] = l[i]*al + rs;
            m[i] = mnew;
            ull alp = pack2(al);
#pragma unroll
            for (int p = 0; p < 4; p++) fmul2(o[i][p], o[i][p], alp);
            *(float4*)&Ps[ty*4+i][tx*4]    = make_float4(e[0], e[1], e[2], e[3]);
            *(float4*)&Ps[ty*4+i][tx*4+32] = make_float4(e[4], e[5], e[6], e[7]);
        }
        __syncthreads();

        // O += P * V
#pragma unroll 4
        for (int j4 = 0; j4 < 64; j4 += 4) {
            float p4[4][4];
#pragma unroll
            for (int i = 0; i < 4; i++)
                *(float4*)p4[i] = *(const float4*)&Ps[ty*4+i][j4];
#pragma unroll
            for (int u = 0; u < 4; u++) {
                double2 t0 = *(const double2*)&Vs[j4+u][tx*4];
                double2 t1 = *(const double2*)&Vs[j4+u][tx*4+32];
                ull b0 = d2u(t0.x), b1 = d2u(t0.y), b2 = d2u(t1.x), b3 = d2u(t1.y);
#pragma unroll
                for (int i = 0; i < 4; i++) {
                    ull a = pack2(p4[i][u]);
                    ffma2(o[i][0], a, b0);
                    ffma2(o[i][1], a, b1);
                    ffma2(o[i][2], a, b2);
                    ffma2(o[i][3], a, b3);
                }
            }
        }
    }

    float* aob = g_ao + (b*S_ + i0)*C_ + h*DK;
#pragma unroll
    for (int i = 0; i < 4; i++) {
        const float inv = 1.0f / l[i];
        float* dst = aob + (ty*4+i)*C_;
        *(float4*)(dst + tx*4) = make_float4(lo2(o[i][0])*inv, hi2(o[i][0])*inv,
                                             lo2(o[i][1])*inv, hi2(o[i][1])*inv);
        *(float4*)(dst + tx*4 + 32) = make_float4(lo2(o[i][2])*inv, hi2(o[i][2])*inv,
                                                  lo2(o[i][3])*inv, hi2(o[i][3])*inv);
    }
}

// ---------------------------------------------------------------------------
// Kernel 3: out-proj + bias + residual. out[b,c,s] = ao[b,s,:] @ w_out[:,c]
// + b_out[c] + x[b,c,s]. Tile 128(c) x 128(s) x 16(n). Same micro layout.
// grid (2, 8, 16).
// ---------------------------------------------------------------------------
__global__ __launch_bounds__(256, 2) void proj_kernel(const float* __restrict__ wo,
                                                      const float* __restrict__ bo,
                                                      const float* __restrict__ x,
                                                      float* __restrict__ out) {
    __shared__ float Ws[16][128];   // [k=n][c]
    __shared__ float At[16][132];   // [k=n][s], padded (16B-aligned rows)
    const int c0 = blockIdx.x*128, s0 = blockIdx.y*128, b = blockIdx.z;
    const int tid = threadIdx.x;
    const int tx = tid & 7, ty = tid >> 3;
    const int lr = tid >> 5, lc = (tid & 31)*4;
    const int srow0 = tid >> 2, kc0 = (tid & 3)*4;   // At transpose loader
    const float* aob = g_ao + (b*S_ + s0)*C_;

    float4 pw0 = *(const float4*)(wo + lr*C_ + c0 + lc);
    float4 pw1 = *(const float4*)(wo + (lr+8)*C_ + c0 + lc);
    float4 pa0 = *(const float4*)(aob + srow0*C_ + kc0);
    float4 pa1 = *(const float4*)(aob + (srow0+64)*C_ + kc0);

    ull acc[4][8];
#pragma unroll
    for (int i = 0; i < 4; i++)
#pragma unroll
        for (int p = 0; p < 8; p++) acc[i][p] = 0ull;

    for (int k0 = 0; k0 < C_; k0 += 16) {
        *(float4*)&Ws[lr][lc]   = pw0;
        *(float4*)&Ws[lr+8][lc] = pw1;
        At[kc0+0][srow0] = pa0.x; At[kc0+1][srow0] = pa0.y;
        At[kc0+2][srow0] = pa0.z; At[kc0+3][srow0] = pa0.w;
        At[kc0+0][srow0+64] = pa1.x; At[kc0+1][srow0+64] = pa1.y;
        At[kc0+2][srow0+64] = pa1.z; At[kc0+3][srow0+64] = pa1.w;
        __syncthreads();
        if (k0 + 16 < C_) {
            pw0 = *(const float4*)(wo + (k0+16+lr)*C_ + c0 + lc);
            pw1 = *(const float4*)(wo + (k0+16+lr+8)*C_ + c0 + lc);
            pa0 = *(const float4*)(aob + srow0*C_ + k0+16 + kc0);
            pa1 = *(const float4*)(aob + (srow0+64)*C_ + k0+16 + kc0);
        }
#pragma unroll
        for (int kk = 0; kk < 16; kk++) {
            float4 av = *(const float4*)&Ws[kk][ty*4];
            ull bp[8];
#pragma unroll
            for (int g = 0; g < 4; g++) {
                double2 t = *(const double2*)&At[kk][tx*4 + g*32];
                bp[g*2]   = d2u(t.x);
                bp[g*2+1] = d2u(t.y);
            }
            ull a0 = pack2(av.x), a1 = pack2(av.y), a2 = pack2(av.z), a3 = pack2(av.w);
#pragma unroll
            for (int p = 0; p < 8; p++) {
                ffma2(acc[0][p], a0, bp[p]);
                ffma2(acc[1][p], a1, bp[p]);
                ffma2(acc[2][p], a2, bp[p]);
                ffma2(acc[3][p], a3, bp[p]);
            }
        }
        __syncthreads();
    }

#pragma unroll
    for (int i = 0; i < 4; i++) {
        const int c = c0 + ty*4 + i;
        const float bias = bo[c];
        const float* xr = x   + (b*C_ + c)*S_ + s0;
        float*       orr = out + (b*C_ + c)*S_ + s0;
#pragma unroll
        for (int g = 0; g < 4; g++) {
            const int sc = tx*4 + g*32;
            float4 xv = *(const float4*)(xr + sc);
            float4 r;
            r.x = lo2(acc[i][2*g])   + bias + xv.x;
            r.y = hi2(acc[i][2*g])   + bias + xv.y;
            r.z = lo2(acc[i][2*g+1]) + bias + xv.z;
            r.w = hi2(acc[i][2*g+1]) + bias + xv.w;
            *(float4*)(orr + sc) = r;
        }
    }
}

// ---------------------------------------------------------------------------
extern "C" void kernel_launch(void* const* d_in, const int* in_sizes, int n_in,
                              void* d_out, int out_size) {
    const float* x     = (const float*)d_in[0];
    const float* w_qkv = (const float*)d_in[1];
    const float* b_qkv = (const float*)d_in[2];
    const float* w_out = (const float*)d_in[3];
    const float* b_out = (const float*)d_in[4];
    float* out = (float*)d_out;

    cudaFuncSetAttribute(attn_kernel, cudaFuncAttributeMaxDynamicSharedMemorySize, 98304);

    qkv_kernel <<<dim3(NQKV/128, S_/128, B_), 256>>>(x, w_qkv, b_qkv);
    attn_kernel<<<dim3(S_/128, NH, B_), 256, 98304>>>();
    proj_kernel<<<dim3(C_/128, S_/128, B_), 256>>>(w_out, b_out, x, out);
}